// round 1
// baseline (speedup 1.0000x reference)
#include <cuda_runtime.h>

// Problem constants (fixed by the reference)
#define N_PTS   16384
#define M_REF   4096
#define L_LAYERS 8
#define S_SPLIT 8
#define CHUNK   (M_REF / S_SPLIT)   // 512 reference vectors per m-chunk
#define TPB     256

// Scratch (no allocations allowed -> __device__ globals)
__device__ float4 g_bref[M_REF];                 // [sin g0, sin g1, cos g0, cos g1]
__device__ float4 g_afeat[N_PTS];                // [sin f0, sin f1, cos f0, cos f1] * 2*log2(e)
__device__ float  g_partial[S_SPLIT * N_PTS];

__device__ __forceinline__ float ex2_approx(float d) {
    float r;
    asm("ex2.approx.ftz.f32 %0, %1;" : "=f"(r) : "f"(d));
    return r;
}

// -------------------------------------------------------------------------
// Kernel A: per-n 8-layer tanh chain -> scaled phi features; per-m phi(ref)
// -------------------------------------------------------------------------
__global__ void precompute_kernel(const float* __restrict__ x,
                                  const float* __restrict__ layer_W,
                                  const float* __restrict__ layer_b,
                                  const float* __restrict__ layer_scale,
                                  const float* __restrict__ layer_shift,
                                  const float* __restrict__ refset)
{
    int i = blockIdx.x * blockDim.x + threadIdx.x;

    if (i < M_REF) {
        float g0 = refset[2 * i + 0];
        float g1 = refset[2 * i + 1];
        float s0, c0, s1, c1;
        sincosf(g0, &s0, &c0);
        sincosf(g1, &s1, &c1);
        g_bref[i] = make_float4(s0, s1, c0, c1);
    }

    if (i < N_PTS) {
        float h0 = x[2 * i + 0];
        float h1 = x[2 * i + 1];
        #pragma unroll
        for (int l = 0; l < L_LAYERS; l++) {
            // layer_W[l] is [2,2] row-major; h @ W^T -> out_j = sum_i h_i * W[j][i]
            float w00 = layer_W[l * 4 + 0], w01 = layer_W[l * 4 + 1];
            float w10 = layer_W[l * 4 + 2], w11 = layer_W[l * 4 + 3];
            float b0  = layer_b[l * 2 + 0],  b1  = layer_b[l * 2 + 1];
            float sc0 = layer_scale[l * 2 + 0], sc1 = layer_scale[l * 2 + 1];
            float t0  = layer_shift[l * 2 + 0], t1  = layer_shift[l * 2 + 1];
            float u0 = tanhf(fmaf(h0, w00, fmaf(h1, w01, b0)));
            float u1 = tanhf(fmaf(h0, w10, fmaf(h1, w11, b1)));
            h0 = fmaf(u0, sc0, t0);
            h1 = fmaf(u1, sc1, t1);
        }
        const float TWO_LOG2E = 2.8853900817779268f;  // 2*log2(e)
        float s0, c0, s1, c1;
        sincosf(h0, &s0, &c0);
        sincosf(h1, &s1, &c1);
        g_afeat[i] = make_float4(s0 * TWO_LOG2E, s1 * TWO_LOG2E,
                                 c0 * TWO_LOG2E, c1 * TWO_LOG2E);
    }
}

// -------------------------------------------------------------------------
// Kernel B: dominant N x M kernel-sum.
//   k(n,m) = exp(2*dot(a,b) - 4) = 2^( C + a' . b ),  C = -4*log2(e)
// grid.x = n-blocks (64), grid.y = m-chunk (8). Each thread: one n, 512 m.
// -------------------------------------------------------------------------
__global__ void __launch_bounds__(TPB) kernel_sum_kernel()
{
    __shared__ float4 sh[CHUNK];  // 8 KB

    const int s = blockIdx.y;
    const int n = blockIdx.x * TPB + threadIdx.x;

    const float4* src = g_bref + s * CHUNK;
    #pragma unroll
    for (int i = threadIdx.x; i < CHUNK; i += TPB) sh[i] = src[i];
    __syncthreads();

    const float4 a = g_afeat[n];
    const float  C = -5.7707801635558536f;  // -4*log2(e)

    float acc0 = 0.f, acc1 = 0.f, acc2 = 0.f, acc3 = 0.f;

    #pragma unroll 4
    for (int m = 0; m < CHUNK; m += 4) {
        float4 b0 = sh[m + 0];
        float4 b1 = sh[m + 1];
        float4 b2 = sh[m + 2];
        float4 b3 = sh[m + 3];
        float d0 = fmaf(a.x, b0.x, fmaf(a.y, b0.y, fmaf(a.z, b0.z, fmaf(a.w, b0.w, C))));
        float d1 = fmaf(a.x, b1.x, fmaf(a.y, b1.y, fmaf(a.z, b1.z, fmaf(a.w, b1.w, C))));
        float d2 = fmaf(a.x, b2.x, fmaf(a.y, b2.y, fmaf(a.z, b2.z, fmaf(a.w, b2.w, C))));
        float d3 = fmaf(a.x, b3.x, fmaf(a.y, b3.y, fmaf(a.z, b3.z, fmaf(a.w, b3.w, C))));
        acc0 += ex2_approx(d0);
        acc1 += ex2_approx(d1);
        acc2 += ex2_approx(d2);
        acc3 += ex2_approx(d3);
    }

    g_partial[s * N_PTS + n] = (acc0 + acc1) + (acc2 + acc3);
}

// -------------------------------------------------------------------------
// Kernel C: reduce partials, mean, tiny MLP, 2-way softmax
// -------------------------------------------------------------------------
__global__ void finalize_kernel(const float* __restrict__ W1,
                                const float* __restrict__ b1,
                                const float* __restrict__ W2,
                                const float* __restrict__ b2,
                                float* __restrict__ out)
{
    int n = blockIdx.x * blockDim.x + threadIdx.x;
    if (n >= N_PTS) return;

    float acc = 0.f;
    #pragma unroll
    for (int s = 0; s < S_SPLIT; s++) acc += g_partial[s * N_PTS + n];
    float agg = acc * (1.0f / (float)M_REF);

    float h[4];
    #pragma unroll
    for (int j = 0; j < 4; j++)
        h[j] = tanhf(fmaf(agg, W1[j], b1[j]));   // W1 is [4,1]

    float l0 = b2[0], l1 = b2[1];
    #pragma unroll
    for (int j = 0; j < 4; j++) {
        l0 = fmaf(W2[j],     h[j], l0);          // W2 is [2,4] row-major
        l1 = fmaf(W2[4 + j], h[j], l1);
    }

    float mx = fmaxf(l0, l1);
    float e0 = expf(l0 - mx);
    float e1 = expf(l1 - mx);
    float inv = 1.0f / (e0 + e1);
    out[2 * n + 0] = e0 * inv;
    out[2 * n + 1] = e1 * inv;
}

// -------------------------------------------------------------------------
extern "C" void kernel_launch(void* const* d_in, const int* in_sizes, int n_in,
                              void* d_out, int out_size)
{
    const float* x           = (const float*)d_in[0];
    const float* layer_W     = (const float*)d_in[1];
    const float* layer_b     = (const float*)d_in[2];
    const float* layer_scale = (const float*)d_in[3];
    const float* layer_shift = (const float*)d_in[4];
    const float* refset      = (const float*)d_in[5];
    const float* W1          = (const float*)d_in[6];
    const float* b1          = (const float*)d_in[7];
    const float* W2          = (const float*)d_in[8];
    const float* b2          = (const float*)d_in[9];
    float* out = (float*)d_out;

    precompute_kernel<<<(N_PTS + 255) / 256, 256>>>(x, layer_W, layer_b,
                                                    layer_scale, layer_shift, refset);

    dim3 grid(N_PTS / TPB, S_SPLIT);
    kernel_sum_kernel<<<grid, TPB>>>();

    finalize_kernel<<<(N_PTS + 255) / 256, 256>>>(W1, b1, W2, b2, out);
}

// round 2
// speedup vs baseline: 2.4025x; 2.4025x over previous
#include <cuda_runtime.h>

// Problem constants
#define N_PTS   16384
#define M_REF   4096
#define L_LAYERS 8
#define KMAX    9                    // Fourier order; trunc err ~ 2*I_10(2) ~ 6e-7
#define RNK     (2*KMAX + 1)         // 19 features per coordinate
#define R2      (RNK*RNK)            // 361
#define SBLK    32                   // blocks computing S partials
#define MPB     (M_REF / SBLK)       // 128 reference points per S-block
#define TPB     128

// Scratch (device globals; no allocation allowed)
__device__ float g_feats[2 * N_PTS];
__device__ float g_Spart[SBLK * R2];

// c_0 = I_0(2), c_k = 2*I_k(2)
__device__ const float C_BES[KMAX + 1] = {
    2.27958530f, 3.18127371f, 1.37789690f, 0.42547992f, 0.10145714f,
    0.01965136f, 0.00320035f, 4.4927400e-4f, 5.5399000e-5f, 6.0876000e-6f
};

__device__ __forceinline__ float ex2_approx(float d) {
    float r;
    asm("ex2.approx.ftz.f32 %0, %1;" : "=f"(r) : "f"(d));
    return r;
}
__device__ __forceinline__ float rcp_approx(float d) {
    float r;
    asm("rcp.approx.ftz.f32 %0, %1;" : "=f"(r) : "f"(d));
    return r;
}
// tanh via e^{2x}: (e-1)/(e+1) = 1 - 2/(e+1). Handles saturation correctly
// (e->inf => 1, e->0 => -1). Rel err ~1e-6.
__device__ __forceinline__ float fast_tanh(float x) {
    float e = ex2_approx(x * 2.8853900817779268f);   // e^{2x}
    return fmaf(-2.0f, rcp_approx(e + 1.0f), 1.0f);
}

// Fourier features of an angle: out[0..KMAX] = w_k cos(k*ang),
// out[KMAX+k] = w_k sin(k*ang) for k=1..KMAX. Chebyshev recurrence.
template <bool WEIGHTED>
__device__ __forceinline__ void four_feats(float ang, float* out) {
    float s, c;
    sincosf(ang, &s, &c);
    float c2 = 2.0f * c;
    float ckm = 1.0f, skm = 0.0f;   // k=0
    float ck  = c,    sk  = s;      // k=1
    out[0] = WEIGHTED ? C_BES[0] : 1.0f;
    #pragma unroll
    for (int k = 1; k <= KMAX; k++) {
        float w = WEIGHTED ? C_BES[k] : 1.0f;
        out[k]        = w * ck;
        out[KMAX + k] = w * sk;
        float cn = fmaf(c2, ck, -ckm);
        float sn = fmaf(c2, sk, -skm);
        ckm = ck; skm = sk; ck = cn; sk = sn;
    }
}

// -------------------------------------------------------------------------
// Kernel 1: blocks [0,32): partial S matrices over 128 reference points each.
//           blocks [32,160): 8-layer tanh chain for 128 data points each.
// -------------------------------------------------------------------------
__global__ void __launch_bounds__(TPB) prep_kernel(
    const float* __restrict__ x,
    const float* __restrict__ layer_W,
    const float* __restrict__ layer_b,
    const float* __restrict__ layer_scale,
    const float* __restrict__ layer_shift,
    const float* __restrict__ refset)
{
    __shared__ float V0[MPB][RNK];
    __shared__ float V1[MPB][RNK];

    int b = blockIdx.x;
    if (b < SBLK) {
        int m = b * MPB + threadIdx.x;
        float g0 = refset[2 * m + 0];
        float g1 = refset[2 * m + 1];
        float v0[RNK], v1[RNK];
        four_feats<true>(g0, v0);
        four_feats<true>(g1, v1);
        #pragma unroll
        for (int i = 0; i < RNK; i++) {
            V0[threadIdx.x][i] = v0[i];
            V1[threadIdx.x][i] = v1[i];
        }
        __syncthreads();

        for (int e = threadIdx.x; e < R2; e += TPB) {
            int j = e / RNK;
            int k = e - j * RNK;
            float acc = 0.0f;
            #pragma unroll 8
            for (int mm = 0; mm < MPB; mm++)
                acc = fmaf(V0[mm][j], V1[mm][k], acc);
            g_Spart[b * R2 + e] = acc;
        }
    } else {
        int n = (b - SBLK) * TPB + threadIdx.x;
        float h0 = x[2 * n + 0];
        float h1 = x[2 * n + 1];
        #pragma unroll
        for (int l = 0; l < L_LAYERS; l++) {
            float w00 = layer_W[l * 4 + 0], w01 = layer_W[l * 4 + 1];
            float w10 = layer_W[l * 4 + 2], w11 = layer_W[l * 4 + 3];
            float b0  = layer_b[l * 2 + 0],  b1  = layer_b[l * 2 + 1];
            float sc0 = layer_scale[l * 2 + 0], sc1 = layer_scale[l * 2 + 1];
            float t0  = layer_shift[l * 2 + 0], t1  = layer_shift[l * 2 + 1];
            float u0 = fast_tanh(fmaf(h0, w00, fmaf(h1, w01, b0)));
            float u1 = fast_tanh(fmaf(h0, w10, fmaf(h1, w11, b1)));
            h0 = fmaf(u0, sc0, t0);
            h1 = fmaf(u1, sc1, t1);
        }
        g_feats[2 * n + 0] = h0;
        g_feats[2 * n + 1] = h1;
    }
}

// -------------------------------------------------------------------------
// Kernel 2: reduce S partials, bilinear form per n, MLP + softmax.
// -------------------------------------------------------------------------
__global__ void __launch_bounds__(TPB) final_kernel(
    const float* __restrict__ W1,
    const float* __restrict__ b1,
    const float* __restrict__ W2,
    const float* __restrict__ b2,
    float* __restrict__ out)
{
    __shared__ float S[R2];

    for (int e = threadIdx.x; e < R2; e += TPB) {
        float acc = 0.0f;
        #pragma unroll
        for (int p = 0; p < SBLK; p++)
            acc += g_Spart[p * R2 + e];
        S[e] = acc;
    }
    __syncthreads();

    int n = blockIdx.x * TPB + threadIdx.x;
    float f0 = g_feats[2 * n + 0];
    float f1 = g_feats[2 * n + 1];

    float u0[RNK], u1[RNK];
    four_feats<false>(f0, u0);
    four_feats<false>(f1, u1);

    // agg = (e^{-4}/M) * u0^T S u1
    float agg = 0.0f;
    #pragma unroll
    for (int j = 0; j < RNK; j++) {
        float t = 0.0f;
        #pragma unroll
        for (int k = 0; k < RNK; k++)
            t = fmaf(S[j * RNK + k], u1[k], t);
        agg = fmaf(u0[j], t, agg);
    }
    agg *= 4.4711032452e-6f;   // exp(-4) / 4096

    // tiny MLP + 2-way softmax
    float h[4];
    #pragma unroll
    for (int j = 0; j < 4; j++)
        h[j] = tanhf(fmaf(agg, W1[j], b1[j]));

    float l0 = b2[0], l1 = b2[1];
    #pragma unroll
    for (int j = 0; j < 4; j++) {
        l0 = fmaf(W2[j],     h[j], l0);
        l1 = fmaf(W2[4 + j], h[j], l1);
    }

    float mx = fmaxf(l0, l1);
    float e0 = expf(l0 - mx);
    float e1 = expf(l1 - mx);
    float inv = 1.0f / (e0 + e1);
    out[2 * n + 0] = e0 * inv;
    out[2 * n + 1] = e1 * inv;
}

// -------------------------------------------------------------------------
extern "C" void kernel_launch(void* const* d_in, const int* in_sizes, int n_in,
                              void* d_out, int out_size)
{
    const float* x           = (const float*)d_in[0];
    const float* layer_W     = (const float*)d_in[1];
    const float* layer_b     = (const float*)d_in[2];
    const float* layer_scale = (const float*)d_in[3];
    const float* layer_shift = (const float*)d_in[4];
    const float* refset      = (const float*)d_in[5];
    const float* W1          = (const float*)d_in[6];
    const float* b1          = (const float*)d_in[7];
    const float* W2          = (const float*)d_in[8];
    const float* b2          = (const float*)d_in[9];
    float* out = (float*)d_out;

    prep_kernel<<<SBLK + N_PTS / TPB, TPB>>>(x, layer_W, layer_b,
                                             layer_scale, layer_shift, refset);
    final_kernel<<<N_PTS / TPB, TPB>>>(W1, b1, W2, b2, out);
}

// round 3
// speedup vs baseline: 2.4085x; 1.0025x over previous
#include <cuda_runtime.h>

// Problem constants
#define N_PTS   16384
#define M_REF   4096
#define L_LAYERS 8
#define KMAX    9                    // Fourier order; trunc err ~ 2*I_10(2) ~ 6e-7
#define RNK     (2*KMAX + 1)         // 19 features per coordinate
#define RPAD    20                   // padded row length (float4-aligned)
#define R2      (RNK*RNK)            // 361
#define SBLK    32                   // blocks computing S partials
#define MPB     (M_REF / SBLK)       // 128 reference points per S-block
#define TPB     128

// Scratch (device globals; no allocation allowed)
__device__ float g_feats[2 * N_PTS];
__device__ float g_Spart[SBLK * R2];
__device__ float g_S[RNK * RPAD];            // reduced + scaled, row-padded

// c_0 = I_0(2), c_k = 2*I_k(2)
__device__ const float C_BES[KMAX + 1] = {
    2.27958530f, 3.18127371f, 1.37789690f, 0.42547992f, 0.10145714f,
    0.01965136f, 0.00320035f, 4.4927400e-4f, 5.5399000e-5f, 6.0876000e-6f
};

__device__ __forceinline__ float ex2_approx(float d) {
    float r; asm("ex2.approx.ftz.f32 %0, %1;" : "=f"(r) : "f"(d)); return r;
}
__device__ __forceinline__ float rcp_approx(float d) {
    float r; asm("rcp.approx.ftz.f32 %0, %1;" : "=f"(r) : "f"(d)); return r;
}
// tanh via e^{2x}: 1 - 2/(e^{2x}+1). Saturates correctly. Rel err ~1e-6.
__device__ __forceinline__ float fast_tanh(float x) {
    float e = ex2_approx(x * 2.8853900817779268f);
    return fmaf(-2.0f, rcp_approx(e + 1.0f), 1.0f);
}

// Fourier features via MUFU sin/cos + Chebyshev recurrence.
// out[0..KMAX] = w_k cos(k a); out[KMAX+k] = w_k sin(k a), k=1..KMAX.
template <bool WEIGHTED>
__device__ __forceinline__ void four_feats(float ang, float* out) {
    float s = __sinf(ang);
    float c = __cosf(ang);
    float c2 = 2.0f * c;
    float ckm = 1.0f, skm = 0.0f;
    float ck  = c,    sk  = s;
    out[0] = WEIGHTED ? C_BES[0] : 1.0f;
    #pragma unroll
    for (int k = 1; k <= KMAX; k++) {
        float w = WEIGHTED ? C_BES[k] : 1.0f;
        out[k]        = w * ck;
        out[KMAX + k] = w * sk;
        float cn = fmaf(c2, ck, -ckm);
        float sn = fmaf(c2, sk, -skm);
        ckm = ck; skm = sk; ck = cn; sk = sn;
    }
}

// -------------------------------------------------------------------------
// Kernel 1: blocks [0,32): partial S matrices (128 ref points each)
//           blocks [32,160): 8-layer tanh chain (128 data points each)
// -------------------------------------------------------------------------
__global__ void __launch_bounds__(TPB) prep_kernel(
    const float* __restrict__ x,
    const float* __restrict__ layer_W,
    const float* __restrict__ layer_b,
    const float* __restrict__ layer_scale,
    const float* __restrict__ layer_shift,
    const float* __restrict__ refset)
{
    __shared__ float V0[MPB][RNK];
    __shared__ float V1[MPB][RNK];

    int b = blockIdx.x;
    if (b < SBLK) {
        int m = b * MPB + threadIdx.x;
        float g0 = refset[2 * m + 0];
        float g1 = refset[2 * m + 1];
        float v0[RNK], v1[RNK];
        four_feats<true>(g0, v0);
        four_feats<true>(g1, v1);
        #pragma unroll
        for (int i = 0; i < RNK; i++) {
            V0[threadIdx.x][i] = v0[i];
            V1[threadIdx.x][i] = v1[i];
        }
        __syncthreads();

        for (int e = threadIdx.x; e < R2; e += TPB) {
            int j = e / RNK;
            int k = e - j * RNK;
            float a0 = 0.f, a1 = 0.f, a2 = 0.f, a3 = 0.f;
            #pragma unroll
            for (int mm = 0; mm < MPB; mm += 4) {
                a0 = fmaf(V0[mm + 0][j], V1[mm + 0][k], a0);
                a1 = fmaf(V0[mm + 1][j], V1[mm + 1][k], a1);
                a2 = fmaf(V0[mm + 2][j], V1[mm + 2][k], a2);
                a3 = fmaf(V0[mm + 3][j], V1[mm + 3][k], a3);
            }
            g_Spart[b * R2 + e] = (a0 + a1) + (a2 + a3);
        }
    } else {
        int n = (b - SBLK) * TPB + threadIdx.x;
        float h0 = x[2 * n + 0];
        float h1 = x[2 * n + 1];
        #pragma unroll
        for (int l = 0; l < L_LAYERS; l++) {
            float w00 = layer_W[l * 4 + 0], w01 = layer_W[l * 4 + 1];
            float w10 = layer_W[l * 4 + 2], w11 = layer_W[l * 4 + 3];
            float b0  = layer_b[l * 2 + 0],  b1  = layer_b[l * 2 + 1];
            float sc0 = layer_scale[l * 2 + 0], sc1 = layer_scale[l * 2 + 1];
            float t0  = layer_shift[l * 2 + 0], t1  = layer_shift[l * 2 + 1];
            float u0 = fast_tanh(fmaf(h0, w00, fmaf(h1, w01, b0)));
            float u1 = fast_tanh(fmaf(h0, w10, fmaf(h1, w11, b1)));
            h0 = fmaf(u0, sc0, t0);
            h1 = fmaf(u1, sc1, t1);
        }
        g_feats[2 * n + 0] = h0;
        g_feats[2 * n + 1] = h1;
    }
}

// -------------------------------------------------------------------------
// Kernel 2: one block reduces the 32 partial S matrices, scales by e^-4/M,
//           writes row-padded layout (19 rows x 20 floats, pad = 0).
// -------------------------------------------------------------------------
__global__ void __launch_bounds__(512) reduce_kernel()
{
    int e = threadIdx.x;
    if (e < R2) {
        float a0 = 0.f, a1 = 0.f, a2 = 0.f, a3 = 0.f;
        #pragma unroll
        for (int p = 0; p < SBLK; p += 4) {
            a0 += g_Spart[(p + 0) * R2 + e];
            a1 += g_Spart[(p + 1) * R2 + e];
            a2 += g_Spart[(p + 2) * R2 + e];
            a3 += g_Spart[(p + 3) * R2 + e];
        }
        int j = e / RNK;
        int k = e - j * RNK;
        g_S[j * RPAD + k] = ((a0 + a1) + (a2 + a3)) * 4.4711032452e-6f; // e^-4 / 4096
    } else if (e < R2 + RNK) {
        // zero the pad column
        int j = e - R2;
        g_S[j * RPAD + (RPAD - 1)] = 0.0f;
    }
}

// -------------------------------------------------------------------------
// Kernel 3: per-n bilinear form (float4 smem reads) + MLP + softmax.
// -------------------------------------------------------------------------
__global__ void __launch_bounds__(TPB) final_kernel(
    const float* __restrict__ W1,
    const float* __restrict__ b1,
    const float* __restrict__ W2,
    const float* __restrict__ b2,
    float* __restrict__ out)
{
    __shared__ __align__(16) float S[RNK * RPAD];

    #pragma unroll
    for (int e = threadIdx.x; e < RNK * RPAD; e += TPB)
        S[e] = g_S[e];
    __syncthreads();

    int n = blockIdx.x * TPB + threadIdx.x;
    float f0 = g_feats[2 * n + 0];
    float f1 = g_feats[2 * n + 1];

    float u0[RNK];
    __align__(16) float u1[RPAD];
    four_feats<false>(f0, u0);
    four_feats<false>(f1, u1);
    u1[RPAD - 1] = 0.0f;

    const float4* u1v = (const float4*)u1;
    float agg = 0.0f;
    #pragma unroll
    for (int j = 0; j < RNK; j++) {
        const float4* Sv = (const float4*)(S + j * RPAD);
        float t0 = 0.f, t1 = 0.f, t2 = 0.f, t3 = 0.f;
        #pragma unroll
        for (int q = 0; q < RPAD / 4; q++) {
            float4 sv = Sv[q];
            float4 uv = u1v[q];
            t0 = fmaf(sv.x, uv.x, t0);
            t1 = fmaf(sv.y, uv.y, t1);
            t2 = fmaf(sv.z, uv.z, t2);
            t3 = fmaf(sv.w, uv.w, t3);
        }
        agg = fmaf(u0[j], (t0 + t1) + (t2 + t3), agg);
    }

    // tiny MLP + 2-way softmax (fast approx, err ~1e-6)
    float h[4];
    #pragma unroll
    for (int j = 0; j < 4; j++)
        h[j] = fast_tanh(fmaf(agg, W1[j], b1[j]));

    float l0 = b2[0], l1 = b2[1];
    #pragma unroll
    for (int j = 0; j < 4; j++) {
        l0 = fmaf(W2[j],     h[j], l0);
        l1 = fmaf(W2[4 + j], h[j], l1);
    }

    const float LOG2E = 1.4426950408889634f;
    float mx = fmaxf(l0, l1);
    float e0 = ex2_approx((l0 - mx) * LOG2E);
    float e1 = ex2_approx((l1 - mx) * LOG2E);
    float inv = rcp_approx(e0 + e1);
    out[2 * n + 0] = e0 * inv;
    out[2 * n + 1] = e1 * inv;
}

// -------------------------------------------------------------------------
extern "C" void kernel_launch(void* const* d_in, const int* in_sizes, int n_in,
                              void* d_out, int out_size)
{
    const float* x           = (const float*)d_in[0];
    const float* layer_W     = (const float*)d_in[1];
    const float* layer_b     = (const float*)d_in[2];
    const float* layer_scale = (const float*)d_in[3];
    const float* layer_shift = (const float*)d_in[4];
    const float* refset      = (const float*)d_in[5];
    const float* W1          = (const float*)d_in[6];
    const float* b1          = (const float*)d_in[7];
    const float* W2          = (const float*)d_in[8];
    const float* b2          = (const float*)d_in[9];
    float* out = (float*)d_out;

    prep_kernel<<<SBLK + N_PTS / TPB, TPB>>>(x, layer_W, layer_b,
                                             layer_scale, layer_shift, refset);
    reduce_kernel<<<1, 512>>>();
    final_kernel<<<N_PTS / TPB, TPB>>>(W1, b1, W2, b2, out);
}

// round 4
// speedup vs baseline: 2.8687x; 1.1910x over previous
#include <cuda_runtime.h>

// Problem constants
#define N_PTS   16384
#define M_REF   4096
#define L_LAYERS 8
#define KMAX    7                    // Fourier order; trunc err ~ 2*sum_{k>7} I_k(2) ~ 6e-5
#define RNK     (2*KMAX + 1)         // 15 features per coordinate
#define RPAD    16                   // padded row length (float4-aligned)
#define R2      (RNK*RNK)            // 225
#define SPAD    (RNK*RPAD)           // 240
#define SBLK    32                   // blocks computing S partials
#define MPB     128                  // reference points per S-block
#define TPB     128
#define SCALE   4.4711032452e-6f     // exp(-4) / 4096

// Scratch (device globals; no allocation allowed)
__device__ float2 g_feats[N_PTS];
__device__ float  g_SpartT[R2 * SBLK];   // transposed: [e][p] for coalesced reduce

// c_0 = I_0(2), c_k = 2*I_k(2)
__constant__ float C_BES[KMAX + 1] = {
    2.27958530f, 3.18127371f, 1.37789690f, 0.42547992f,
    0.10145715f, 0.01965093f, 3.2003260e-3f, 4.4927600e-4f
};

__device__ __forceinline__ float ex2_approx(float d) {
    float r; asm("ex2.approx.ftz.f32 %0, %1;" : "=f"(r) : "f"(d)); return r;
}
__device__ __forceinline__ float rcp_approx(float d) {
    float r; asm("rcp.approx.ftz.f32 %0, %1;" : "=f"(r) : "f"(d)); return r;
}
// tanh via e^{2x}: 1 - 2/(e^{2x}+1). Saturates correctly. Rel err ~1e-6.
__device__ __forceinline__ float fast_tanh(float x) {
    float e = ex2_approx(x * 2.8853900817779268f);
    return fmaf(-2.0f, rcp_approx(e + 1.0f), 1.0f);
}

// Fourier features via MUFU sin/cos + Chebyshev recurrence.
// out[0] = w0; out[k] = w_k cos(k a); out[KMAX+k] = w_k sin(k a), k=1..KMAX.
// WEIGHTED: w_k = C_BES[k] * wscale;  else w_k = 1.
template <bool WEIGHTED>
__device__ __forceinline__ void four_feats(float ang, float* out, float wscale) {
    float s = __sinf(ang);
    float c = __cosf(ang);
    float c2 = 2.0f * c;
    float ckm = 1.0f, skm = 0.0f;
    float ck  = c,    sk  = s;
    out[0] = WEIGHTED ? C_BES[0] * wscale : 1.0f;
    #pragma unroll
    for (int k = 1; k <= KMAX; k++) {
        float w = WEIGHTED ? C_BES[k] * wscale : 1.0f;
        out[k]        = w * ck;
        out[KMAX + k] = w * sk;
        float cn = fmaf(c2, ck, -ckm);
        float sn = fmaf(c2, sk, -skm);
        ckm = ck; skm = sk; ck = cn; sk = sn;
    }
}

// -------------------------------------------------------------------------
// Kernel 1: blocks [0,32):  partial S matrices (128 ref points each),
//                           written transposed g_SpartT[e*SBLK + b].
//           blocks [32,160): 8-layer tanh chain (128 data points each).
// -------------------------------------------------------------------------
__global__ void __launch_bounds__(TPB) prep_kernel(
    const float* __restrict__ x,
    const float* __restrict__ layer_W,
    const float* __restrict__ layer_b,
    const float* __restrict__ layer_scale,
    const float* __restrict__ layer_shift,
    const float* __restrict__ refset)
{
    __shared__ float V0[MPB][RNK];
    __shared__ float V1[MPB][RNK];

    int b = blockIdx.x;
    if (b < SBLK) {
        int m = b * MPB + threadIdx.x;
        float g0 = refset[2 * m + 0];
        float g1 = refset[2 * m + 1];
        float v0[RNK], v1[RNK];
        four_feats<true>(g0, v0, SCALE);   // e^-4/M folded into v0 weights
        four_feats<true>(g1, v1, 1.0f);
        #pragma unroll
        for (int i = 0; i < RNK; i++) {
            V0[threadIdx.x][i] = v0[i];
            V1[threadIdx.x][i] = v1[i];
        }
        __syncthreads();

        int e0 = threadIdx.x;            // < 128, always valid (R2=225)
        int e1 = threadIdx.x + TPB;      // valid if < 225
        int j0 = e0 / RNK, k0 = e0 - j0 * RNK;
        int j1 = e1 / RNK, k1 = e1 - j1 * RNK;
        bool has1 = (e1 < R2);

        float a0 = 0.f, a1 = 0.f, b0 = 0.f, b1 = 0.f;
        #pragma unroll 4
        for (int mm = 0; mm < MPB; mm += 2) {
            a0 = fmaf(V0[mm + 0][j0], V1[mm + 0][k0], a0);
            a1 = fmaf(V0[mm + 1][j0], V1[mm + 1][k0], a1);
            if (has1) {
                b0 = fmaf(V0[mm + 0][j1], V1[mm + 0][k1], b0);
                b1 = fmaf(V0[mm + 1][j1], V1[mm + 1][k1], b1);
            }
        }
        g_SpartT[e0 * SBLK + b] = a0 + a1;
        if (has1) g_SpartT[e1 * SBLK + b] = b0 + b1;
    } else {
        int n = (b - SBLK) * TPB + threadIdx.x;
        float h0 = x[2 * n + 0];
        float h1 = x[2 * n + 1];
        #pragma unroll
        for (int l = 0; l < L_LAYERS; l++) {
            float w00 = layer_W[l * 4 + 0], w01 = layer_W[l * 4 + 1];
            float w10 = layer_W[l * 4 + 2], w11 = layer_W[l * 4 + 3];
            float c0  = layer_b[l * 2 + 0],  c1  = layer_b[l * 2 + 1];
            float sc0 = layer_scale[l * 2 + 0], sc1 = layer_scale[l * 2 + 1];
            float t0  = layer_shift[l * 2 + 0], t1  = layer_shift[l * 2 + 1];
            float u0 = fast_tanh(fmaf(h0, w00, fmaf(h1, w01, c0)));
            float u1 = fast_tanh(fmaf(h0, w10, fmaf(h1, w11, c1)));
            h0 = fmaf(u0, sc0, t0);
            h1 = fmaf(u1, sc1, t1);
        }
        g_feats[n] = make_float2(h0, h1);
    }
}

// -------------------------------------------------------------------------
// Kernel 2: per-block stateless S reduction (16 LDG.128/thread, L2-resident),
//           per-n bilinear form + MLP + softmax.
// -------------------------------------------------------------------------
__global__ void __launch_bounds__(TPB) final_kernel(
    const float* __restrict__ W1,
    const float* __restrict__ b1,
    const float* __restrict__ W2,
    const float* __restrict__ b2,
    float* __restrict__ out)
{
    __shared__ __align__(16) float S[SPAD];   // 15 rows x 16 (pad col = 0)

    int n = blockIdx.x * TPB + threadIdx.x;
    float2 f = g_feats[n];                    // issue early

    // Reduce 32 transposed partials: each thread covers elements tid, tid+128.
    #pragma unroll
    for (int pass = 0; pass < 2; pass++) {
        int e = threadIdx.x + pass * TPB;
        if (e < R2) {
            const float4* src = (const float4*)(g_SpartT + e * SBLK);
            float4 s0 = src[0], s1 = src[1], s2 = src[2], s3 = src[3];
            float4 s4 = src[4], s5 = src[5], s6 = src[6], s7 = src[7];
            float r = (((s0.x + s0.y) + (s0.z + s0.w)) + ((s1.x + s1.y) + (s1.z + s1.w)))
                    + (((s2.x + s2.y) + (s2.z + s2.w)) + ((s3.x + s3.y) + (s3.z + s3.w)))
                    + (((s4.x + s4.y) + (s4.z + s4.w)) + ((s5.x + s5.y) + (s5.z + s5.w)))
                    + (((s6.x + s6.y) + (s6.z + s6.w)) + ((s7.x + s7.y) + (s7.z + s7.w)));
            int j = e / RNK, k = e - j * RNK;
            S[j * RPAD + k] = r;
        } else if (e < SPAD) {
            int j = e - R2;                   // pad column
            S[j * RPAD + (RPAD - 1)] = 0.0f;
        }
    }

    // Trig features (overlaps S-load latency before the sync)
    float u0[RNK];
    __align__(16) float u1[RPAD];
    four_feats<false>(f.x, u0, 1.0f);
    four_feats<false>(f.y, u1, 1.0f);
    u1[RPAD - 1] = 0.0f;

    __syncthreads();

    const float4* u1v = (const float4*)u1;
    float agg = 0.0f;
    #pragma unroll
    for (int j = 0; j < RNK; j++) {
        const float4* Sv = (const float4*)(S + j * RPAD);
        float t0 = 0.f, t1 = 0.f, t2 = 0.f, t3 = 0.f;
        #pragma unroll
        for (int q = 0; q < RPAD / 4; q++) {
            float4 sv = Sv[q];
            float4 uv = u1v[q];
            t0 = fmaf(sv.x, uv.x, t0);
            t1 = fmaf(sv.y, uv.y, t1);
            t2 = fmaf(sv.z, uv.z, t2);
            t3 = fmaf(sv.w, uv.w, t3);
        }
        agg = fmaf(u0[j], (t0 + t1) + (t2 + t3), agg);
    }

    // tiny MLP + 2-way softmax (fast approx)
    float h[4];
    #pragma unroll
    for (int j = 0; j < 4; j++)
        h[j] = fast_tanh(fmaf(agg, W1[j], b1[j]));

    float l0 = b2[0], l1 = b2[1];
    #pragma unroll
    for (int j = 0; j < 4; j++) {
        l0 = fmaf(W2[j],     h[j], l0);
        l1 = fmaf(W2[4 + j], h[j], l1);
    }

    const float LOG2E = 1.4426950408889634f;
    float mx = fmaxf(l0, l1);
    float e0 = ex2_approx((l0 - mx) * LOG2E);
    float e1 = ex2_approx((l1 - mx) * LOG2E);
    float inv = rcp_approx(e0 + e1);
    out[2 * n + 0] = e0 * inv;
    out[2 * n + 1] = e1 * inv;
}

// -------------------------------------------------------------------------
extern "C" void kernel_launch(void* const* d_in, const int* in_sizes, int n_in,
                              void* d_out, int out_size)
{
    const float* x           = (const float*)d_in[0];
    const float* layer_W     = (const float*)d_in[1];
    const float* layer_b     = (const float*)d_in[2];
    const float* layer_scale = (const float*)d_in[3];
    const float* layer_shift = (const float*)d_in[4];
    const float* refset      = (const float*)d_in[5];
    const float* W1          = (const float*)d_in[6];
    const float* b1          = (const float*)d_in[7];
    const float* W2          = (const float*)d_in[8];
    const float* b2          = (const float*)d_in[9];
    float* out = (float*)d_out;

    prep_kernel<<<SBLK + N_PTS / TPB, TPB>>>(x, layer_W, layer_b,
                                             layer_scale, layer_shift, refset);
    final_kernel<<<N_PTS / TPB, TPB>>>(W1, b1, W2, b2, out);
}